// round 4
// baseline (speedup 1.0000x reference)
#include <cuda_runtime.h>
#include <cstdint>

#define B_    32
#define NP    32
#define DPD   12
#define PP    32
#define LL    1024
#define LOUT  32
#define XSTR  16             // floats per staged x column: [x0..x11, x2, 1.0, pad, pad]
#define BIGF  1e30f
#define TPB   128            // 4 warps/CTA -> 256 CTAs -> all 148 SMs busy

__device__ __forceinline__ unsigned long long pk2(float lo, float hi) {
    unsigned long long r;
    asm("mov.b64 %0, {%1,%2};" : "=l"(r) : "f"(lo), "f"(hi));
    return r;
}
__device__ __forceinline__ unsigned long long fma2(unsigned long long a,
                                                   unsigned long long b,
                                                   unsigned long long c) {
    unsigned long long d;
    asm("fma.rn.f32x2 %0, %1, %2, %3;" : "=l"(d) : "l"(a), "l"(b), "l"(c));
    return d;
}
__device__ __forceinline__ unsigned long long add2(unsigned long long a,
                                                   unsigned long long b) {
    unsigned long long d;
    asm("add.rn.f32x2 %0, %1, %2;" : "=l"(d) : "l"(a), "l"(b));
    return d;
}
__device__ __forceinline__ void unpk(unsigned long long v, float& lo, float& hi) {
    asm("mov.b64 {%0,%1}, %2;" : "=f"(lo), "=f"(hi) : "l"(v));
}

// smem: [0, LL*XSTR) floats = staged x (64KB); then 4 rings of 64*32 floats (8KB each)
extern __shared__ float xs[];

__global__ void __launch_bounds__(TPB)
dtw_kernel(const float* __restrict__ x,
           const float* __restrict__ patts,
           float* __restrict__ out)
{
    const int tid  = threadIdx.x;
    const int warp = tid >> 5;
    const int lane = tid & 31;
    const int b    = blockIdx.x >> 3;      // 32 batches
    const int ng   = blockIdx.x & 7;       // 8 groups of 4 patterns
    const int n    = ng * 4 + warp;

    // ---- stage x[b]: column-major per j, stride 16, x2 and 1.0 appended ----
    const float* xb = x + (size_t)b * DPD * LL;
    for (int idx = tid; idx < DPD * LL; idx += TPB) {
        int d = idx >> 10;
        int j = idx & (LL - 1);
        xs[j * XSTR + d] = xb[d * LL + j];
    }
    __syncthreads();
    for (int j = tid; j < LL; j += TPB) {
        float s = 0.f;
        #pragma unroll
        for (int d = 0; d < DPD; ++d) {
            float v = xs[j * XSTR + d];
            s = fmaf(v, v, s);
        }
        xs[j * XSTR + DPD]     = s;
        xs[j * XSTR + DPD + 1] = 1.f;
    }
    __syncthreads();

    // ---- per-lane pattern registers ----
    float p[DPD]; float p2 = 0.f;
    #pragma unroll
    for (int d = 0; d < DPD; ++d) {
        p[d] = patts[(n * DPD + d) * PP + lane];
        p2 = fmaf(p[d], p[d], p2);
    }
    unsigned long long qp[7];
    #pragma unroll
    for (int k = 0; k < 6; ++k) qp[k] = pk2(-2.f * p[2 * k], -2.f * p[2 * k + 1]);
    qp[6] = pk2(1.f, p2);                    // pairs with (x2, 1.0)
    const unsigned long long zero2 = pk2(0.f, 0.f);

    uint32_t xs_base;
    asm("{ .reg .u64 t; cvta.to.shared.u64 t, %1; cvt.u32.u64 %0, t; }"
        : "=r"(xs_base) : "l"(xs));

    // cost(lane, j): broadcast x-column load (uniform address across the warp)
    auto cost_at = [&](int jc) -> float {
        uint32_t a = xs_base + (uint32_t)jc * (XSTR * 4);
        unsigned long long v0, v1, v2, v3, v4, v5, v6;
        asm volatile("ld.shared.v2.u64 {%0,%1}, [%2];"    : "=l"(v0), "=l"(v1) : "r"(a));
        asm volatile("ld.shared.v2.u64 {%0,%1}, [%2+16];" : "=l"(v2), "=l"(v3) : "r"(a));
        asm volatile("ld.shared.v2.u64 {%0,%1}, [%2+32];" : "=l"(v4), "=l"(v5) : "r"(a));
        asm volatile("ld.shared.u64 %0, [%1+48];"         : "=l"(v6) : "r"(a));
        unsigned long long a0 = fma2(qp[0], v0, zero2);
        unsigned long long a1 = fma2(qp[1], v1, zero2);
        a0 = fma2(qp[2], v2, a0);
        a1 = fma2(qp[3], v3, a1);
        a0 = fma2(qp[4], v4, a0);
        a1 = fma2(qp[5], v5, a1);
        a0 = fma2(qp[6], v6, a0);            // adds (x2, p2)
        unsigned long long s = add2(a0, a1);
        float lo, hi; unpk(s, lo, hi);
        return lo + hi;
    };

    // per-warp cost ring: 64 columns x 32 rows; lane writes/reads ONLY its own row
    float* ring = xs + LL * XSTR + warp * (64 * 32);

    // prologue: columns 0..31
    for (int g = 0; g < 32; ++g)
        ring[g * 32 + lane] = cost_at(g);

    // ---- wavefront DP; step t: DP cell (lane, t-lane) + gen column t+32 ----
    float d_prev = BIGF;
    float diag   = (lane == 0) ? 0.f : BIGF;   // makes D[0,0] = c00 without a peel
    float* outp = out + (((size_t)(b * NP + n)) * PP + lane) * LOUT;

    // head: t = 0..30 (some lanes have j < 0); gen cols 32..62
    for (int t = 0; t < 31; ++t) {
        ring[((t + 32) & 63) * 32 + lane] = cost_at(t + 32);
        int j = t - lane;
        float c = ring[(((unsigned)j) & 63u) * 32 + lane];
        float up = __shfl_up_sync(0xffffffffu, d_prev, 1);
        if (lane == 0) up = BIGF;
        float pred  = fminf(fminf(up, d_prev), diag);
        float d_cur = c + pred;
        if (j < 0) d_cur = BIGF;
        diag = up;
        d_prev = d_cur;
    }

    // main: t = 31..991 (all lanes valid, no stores); gen cols 63..1023
    #pragma unroll 4
    for (int t = 31; t < 992; ++t) {
        ring[((t + 32) & 63) * 32 + lane] = cost_at(t + 32);
        float c = ring[(((unsigned)(t - lane)) & 63u) * 32 + lane];
        float up = __shfl_up_sync(0xffffffffu, d_prev, 1);
        if (lane == 0) up = BIGF;
        float m1    = fminf(d_prev, diag);     // off-chain while shfl in flight
        float pred  = fminf(up, m1);
        float d_cur = c + pred;
        diag = up;
        d_prev = d_cur;
    }

    // tail: t = 992..1054 — ring already holds cols 960..1023; stores for j in [992,1024)
    for (int t = 992; t < PP + LL - 1; ++t) {
        int j = t - lane;
        float c = ring[(((unsigned)j) & 63u) * 32 + lane];
        float up = __shfl_up_sync(0xffffffffu, d_prev, 1);
        if (lane == 0) up = BIGF;
        float pred  = fminf(fminf(up, d_prev), diag);
        float d_cur = c + pred;
        unsigned jo = (unsigned)(j - (LL - LOUT));
        if (jo < (unsigned)LOUT) outp[jo] = d_cur;
        diag = up;
        d_prev = d_cur;
    }
}

extern "C" void kernel_launch(void* const* d_in, const int* in_sizes, int n_in,
                              void* d_out, int out_size)
{
    const float* x     = (const float*)d_in[0];   // [32, 12, 1024]
    const float* patts = (const float*)d_in[1];   // [32, 12, 32]
    float* out         = (float*)d_out;           // [32, 32, 32, 32]

    const int smem = (LL * XSTR + 4 * 64 * 32) * sizeof(float);  // 96 KB
    cudaFuncSetAttribute(dtw_kernel, cudaFuncAttributeMaxDynamicSharedMemorySize, smem);
    dtw_kernel<<<B_ * (NP / 4), TPB, smem>>>(x, patts, out);
}

// round 5
// speedup vs baseline: 1.3406x; 1.3406x over previous
#include <cuda_runtime.h>
#include <cstdint>

#define B_    32
#define NP    32
#define DPD   12
#define PP    32
#define LL    1024
#define LOUT  32
#define BIGF  1e30f
#define TPB   256            // 8 warps: 0-3 DP, 4-7 gen
#define CH    16             // chunk columns
#define NPH   66             // ceil(1055/16)
#define RSTR  66             // ring row stride (floats), padded for STS.64 conflicts
// smem floats: x rows [13][1024] (rows 0-11 = x_d, row 12 = x2), then 4 rings [32][66]
#define XWORDS   (13 * 1024)
#define RINGW    (32 * RSTR)
#define SMEMW    (XWORDS + 4 * RINGW)

__device__ __forceinline__ unsigned long long pk2(float lo, float hi) {
    unsigned long long r;
    asm("mov.b64 %0, {%1,%2};" : "=l"(r) : "f"(lo), "f"(hi));
    return r;
}
__device__ __forceinline__ unsigned long long fma2(unsigned long long a,
                                                   unsigned long long b,
                                                   unsigned long long c) {
    unsigned long long d;
    asm("fma.rn.f32x2 %0, %1, %2, %3;" : "=l"(d) : "l"(a), "l"(b), "l"(c));
    return d;
}
__device__ __forceinline__ unsigned long long add2(unsigned long long a,
                                                   unsigned long long b) {
    unsigned long long d;
    asm("add.rn.f32x2 %0, %1, %2;" : "=l"(d) : "l"(a), "l"(b));
    return d;
}
__device__ __forceinline__ void lds2(unsigned long long& a, unsigned long long& b,
                                     uint32_t addr) {
    asm volatile("ld.shared.v2.u64 {%0,%1}, [%2];" : "=l"(a), "=l"(b) : "r"(addr));
}
__device__ __forceinline__ void sts64(uint32_t addr, unsigned long long v) {
    asm volatile("st.shared.b64 [%0], %1;" :: "r"(addr), "l"(v) : "memory");
}
__device__ __forceinline__ float lds32(uint32_t addr) {
    float v;
    asm volatile("ld.shared.f32 %0, [%1];" : "=f"(v) : "r"(addr));
    return v;
}

extern __shared__ float xs[];

__global__ void __launch_bounds__(TPB)
dtw_kernel(const float* __restrict__ x,
           const float* __restrict__ patts,
           float* __restrict__ out)
{
    const int tid  = threadIdx.x;
    const int warp = tid >> 5;
    const int lane = tid & 31;
    const int b    = blockIdx.x >> 3;      // 32 batches
    const int ng   = blockIdx.x & 7;       // 8 groups of 4 patterns

    uint32_t xs_base;
    asm("{ .reg .u64 t; cvta.to.shared.u64 t, %1; cvt.u32.u64 %0, t; }"
        : "=r"(xs_base) : "l"(xs));

    // ---- stage x[b] row-major (direct copy) ----
    {
        const float4* xb4 = (const float4*)(x + (size_t)b * DPD * LL);
        float4* xs4 = (float4*)xs;
        #pragma unroll
        for (int i = tid; i < DPD * LL / 4; i += TPB) xs4[i] = xb4[i];
    }
    __syncthreads();
    // ---- x2 row (row 12) ----
    for (int j = tid; j < LL; j += TPB) {
        float s = 0.f;
        #pragma unroll
        for (int d = 0; d < DPD; ++d) {
            float v = xs[d * LL + j];
            s = fmaf(v, v, s);
        }
        xs[DPD * LL + j] = s;
    }
    __syncthreads();

    const int w  = warp & 3;               // problem index within CTA
    const int n  = ng * 4 + w;
    const bool is_gen = (warp >= 4);

    // ring base for this problem, this lane (bytes)
    const uint32_t ring_lane = xs_base + (uint32_t)(XWORDS + w * RINGW + lane * RSTR) * 4u;

    // ---- gen-warp state: patterns packed for 2-column FMA2 ----
    unsigned long long qpd[DPD];
    unsigned long long p2p = 0;
    if (is_gen) {
        float p2 = 0.f;
        #pragma unroll
        for (int d = 0; d < DPD; ++d) {
            float pv = patts[(n * DPD + d) * PP + lane];
            p2 = fmaf(pv, pv, p2);
            float m = -2.f * pv;
            qpd[d] = pk2(m, m);
        }
        p2p = pk2(p2, p2);
    }

    // gen one 16-column chunk: cost(lane, c0..c0+15) -> ring slot (c0 & 63)
    auto gen_chunk = [&](int chunk) {
        const int c0    = chunk * CH;
        const int slot0 = c0 & 63;
        unsigned long long acc[8];
        // init: x2 pair + (p2,p2)
        {
            uint32_t a2 = xs_base + (uint32_t)(DPD * LL + c0) * 4u;
            unsigned long long v0, v1, v2, v3, v4, v5, v6, v7;
            lds2(v0, v1, a2);       lds2(v2, v3, a2 + 16);
            lds2(v4, v5, a2 + 32);  lds2(v6, v7, a2 + 48);
            acc[0] = add2(v0, p2p); acc[1] = add2(v1, p2p);
            acc[2] = add2(v2, p2p); acc[3] = add2(v3, p2p);
            acc[4] = add2(v4, p2p); acc[5] = add2(v5, p2p);
            acc[6] = add2(v6, p2p); acc[7] = add2(v7, p2p);
        }
        #pragma unroll
        for (int d = 0; d < DPD; ++d) {
            uint32_t ad = xs_base + (uint32_t)(d * LL + c0) * 4u;
            unsigned long long v0, v1, v2, v3, v4, v5, v6, v7;
            lds2(v0, v1, ad);       lds2(v2, v3, ad + 16);
            lds2(v4, v5, ad + 32);  lds2(v6, v7, ad + 48);
            acc[0] = fma2(qpd[d], v0, acc[0]);
            acc[1] = fma2(qpd[d], v1, acc[1]);
            acc[2] = fma2(qpd[d], v2, acc[2]);
            acc[3] = fma2(qpd[d], v3, acc[3]);
            acc[4] = fma2(qpd[d], v4, acc[4]);
            acc[5] = fma2(qpd[d], v5, acc[5]);
            acc[6] = fma2(qpd[d], v6, acc[6]);
            acc[7] = fma2(qpd[d], v7, acc[7]);
        }
        uint32_t sb = ring_lane + (uint32_t)slot0 * 4u;
        #pragma unroll
        for (int k = 0; k < 8; ++k) sts64(sb + 8u * k, acc[k]);
    };

    // ---- DP state ----
    float d_prev = BIGF;
    float diag   = (lane == 0) ? 0.f : BIGF;   // seeds D[0,0] = c(0,0)
    float* outp = out + (((size_t)(b * NP + n)) * PP + lane) * LOUT;

    // prefill chunk 0
    if (is_gen) gen_chunk(0);
    __syncthreads();

    for (int p = 0; p < NPH; ++p) {
        if (is_gen) {
            if (p <= 62) gen_chunk(p + 1);
        } else {
            const int t0 = p * CH;
            if (p < 2) {
                // head: j = t - lane may be < 0
                for (int t = t0; t < t0 + CH; ++t) {
                    int j = t - lane;
                    float c = lds32(ring_lane + (((unsigned)j & 63u) << 2));
                    float up = __shfl_up_sync(0xffffffffu, d_prev, 1);
                    if (lane == 0) up = BIGF;
                    float pred  = fminf(fminf(up, d_prev), diag);
                    float d_cur = c + pred;
                    if (j < 0) d_cur = BIGF;
                    diag = up;
                    d_prev = d_cur;
                }
            } else if (p < 62) {
                // main: all lanes valid, no stores
                int u = t0 - lane;
                #pragma unroll
                for (int s = 0; s < CH; ++s) {
                    float c = lds32(ring_lane + (((unsigned)(u + s) & 63u) << 2));
                    float up = __shfl_up_sync(0xffffffffu, d_prev, 1);
                    if (lane == 0) up = BIGF;
                    float m1 = fminf(d_prev, diag);
                    diag = up;
                    d_prev = fminf(up, m1) + c;
                }
            } else {
                // tail: stores for j in [992, 1024); lanes with j > 1023 run on
                // stale ring data but provably never feed valid cells/stores
                const int t1 = (t0 + CH < PP + LL - 1) ? t0 + CH : PP + LL - 1;
                for (int t = t0; t < t1; ++t) {
                    int j = t - lane;
                    float c = lds32(ring_lane + (((unsigned)j & 63u) << 2));
                    float up = __shfl_up_sync(0xffffffffu, d_prev, 1);
                    if (lane == 0) up = BIGF;
                    float pred  = fminf(fminf(up, d_prev), diag);
                    float d_cur = c + pred;
                    unsigned jo = (unsigned)(j - (LL - LOUT));
                    if (jo < (unsigned)LOUT) outp[jo] = d_cur;
                    diag = up;
                    d_prev = d_cur;
                }
            }
        }
        __syncthreads();
    }
}

extern "C" void kernel_launch(void* const* d_in, const int* in_sizes, int n_in,
                              void* d_out, int out_size)
{
    const float* x     = (const float*)d_in[0];   // [32, 12, 1024]
    const float* patts = (const float*)d_in[1];   // [32, 12, 32]
    float* out         = (float*)d_out;           // [32, 32, 32, 32]

    const int smem = SMEMW * sizeof(float);       // 87040 B -> 2 CTAs/SM
    cudaFuncSetAttribute(dtw_kernel, cudaFuncAttributeMaxDynamicSharedMemorySize, smem);
    dtw_kernel<<<B_ * (NP / 4), TPB, smem>>>(x, patts, out);
}

// round 7
// speedup vs baseline: 1.5521x; 1.1577x over previous
#include <cuda_runtime.h>
#include <cstdint>

#define B_    32
#define NP    32
#define DPD   12
#define LL    1024
#define LOUT  32
#define BIGF  1e30f
#define TPB   192            // 6 warps: 0-1 DP (2 problems each), 2-5 gen (1 each)
#define CH    16
#define NPH   66
#define SLOTM 34             // ring word stride per slot (odd-diff vs row stride 1)
#define RINGW (SLOTM*64 + 1) // 2177 words/problem; +1 pad shifts banks between pair
#define XWORDS (13*1024)     // x rows 0-11 + x2 row 12
#define SMEMW (XWORDS + 4*RINGW)

__device__ __forceinline__ unsigned long long pk2(float lo, float hi) {
    unsigned long long r;
    asm("mov.b64 %0, {%1,%2};" : "=l"(r) : "f"(lo), "f"(hi));
    return r;
}
__device__ __forceinline__ unsigned long long fma2(unsigned long long a,
                                                   unsigned long long b,
                                                   unsigned long long c) {
    unsigned long long d;
    asm("fma.rn.f32x2 %0, %1, %2, %3;" : "=l"(d) : "l"(a), "l"(b), "l"(c));
    return d;
}
__device__ __forceinline__ unsigned long long add2(unsigned long long a,
                                                   unsigned long long b) {
    unsigned long long d;
    asm("add.rn.f32x2 %0, %1, %2;" : "=l"(d) : "l"(a), "l"(b));
    return d;
}
__device__ __forceinline__ void unpk(unsigned long long v, float& lo, float& hi) {
    asm("mov.b64 {%0,%1}, %2;" : "=f"(lo), "=f"(hi) : "l"(v));
}
__device__ __forceinline__ void lds2(unsigned long long& a, unsigned long long& b,
                                     uint32_t addr) {
    asm volatile("ld.shared.v2.u64 {%0,%1}, [%2];" : "=l"(a), "=l"(b) : "r"(addr));
}
__device__ __forceinline__ void sts32(uint32_t addr, float v) {
    asm volatile("st.shared.f32 [%0], %1;" :: "r"(addr), "f"(v) : "memory");
}
__device__ __forceinline__ float lds32(uint32_t addr) {
    float v;
    asm volatile("ld.shared.f32 %0, [%1];" : "=f"(v) : "r"(addr));
    return v;
}

extern __shared__ float xs[];

__global__ void __launch_bounds__(TPB)
dtw_kernel(const float* __restrict__ x,
           const float* __restrict__ patts,
           float* __restrict__ out)
{
    const int tid  = threadIdx.x;
    const int warp = tid >> 5;
    const int lane = tid & 31;
    const int b    = blockIdx.x >> 3;
    const int ng   = blockIdx.x & 7;

    uint32_t xs_base;
    asm("{ .reg .u64 t; cvta.to.shared.u64 t, %1; cvt.u32.u64 %0, t; }"
        : "=r"(xs_base) : "l"(xs));

    // ---- stage x[b] row-major ----
    {
        const float4* xb4 = (const float4*)(x + (size_t)b * DPD * LL);
        float4* xs4 = (float4*)xs;
        for (int i = tid; i < DPD * LL / 4; i += TPB) xs4[i] = xb4[i];
    }
    __syncthreads();
    for (int j = tid; j < LL; j += TPB) {
        float s = 0.f;
        #pragma unroll
        for (int d = 0; d < DPD; ++d) { float v = xs[d * LL + j]; s = fmaf(v, v, s); }
        xs[DPD * LL + j] = s;
    }
    __syncthreads();

    const bool is_gen = (warp >= 2);

    // ---- gen state (warps 2-5, one problem each) ----
    unsigned long long qpd[DPD];
    unsigned long long p2p = 0;
    uint32_t gring = 0;
    if (is_gen) {
        const int w = warp - 2;
        const int n = ng * 4 + w;
        gring = xs_base + (uint32_t)(XWORDS + w * RINGW) * 4u;
        float p2 = 0.f;
        #pragma unroll
        for (int d = 0; d < DPD; ++d) {
            float pv = patts[(n * DPD + d) * 32 + lane];   // gen lane = pattern row
            p2 = fmaf(pv, pv, p2);
            float m = -2.f * pv;
            qpd[d] = pk2(m, m);
        }
        p2p = pk2(p2, p2);
    }

    // gen one 16-col chunk: cost(lane=row, c0..c0+15) into ring[slot][row]
    auto gen_chunk = [&](int chunk) {
        const int c0 = chunk * CH;
        const int s0 = c0 & 63;
        unsigned long long acc[8];
        {
            uint32_t a2 = xs_base + (uint32_t)(DPD * LL + c0) * 4u;
            unsigned long long v0, v1, v2, v3, v4, v5, v6, v7;
            lds2(v0, v1, a2);       lds2(v2, v3, a2 + 16);
            lds2(v4, v5, a2 + 32);  lds2(v6, v7, a2 + 48);
            acc[0] = add2(v0, p2p); acc[1] = add2(v1, p2p);
            acc[2] = add2(v2, p2p); acc[3] = add2(v3, p2p);
            acc[4] = add2(v4, p2p); acc[5] = add2(v5, p2p);
            acc[6] = add2(v6, p2p); acc[7] = add2(v7, p2p);
        }
        #pragma unroll
        for (int d = 0; d < DPD; ++d) {
            uint32_t ad = xs_base + (uint32_t)(d * LL + c0) * 4u;
            unsigned long long v0, v1, v2, v3, v4, v5, v6, v7;
            lds2(v0, v1, ad);       lds2(v2, v3, ad + 16);
            lds2(v4, v5, ad + 32);  lds2(v6, v7, ad + 48);
            acc[0] = fma2(qpd[d], v0, acc[0]);
            acc[1] = fma2(qpd[d], v1, acc[1]);
            acc[2] = fma2(qpd[d], v2, acc[2]);
            acc[3] = fma2(qpd[d], v3, acc[3]);
            acc[4] = fma2(qpd[d], v4, acc[4]);
            acc[5] = fma2(qpd[d], v5, acc[5]);
            acc[6] = fma2(qpd[d], v6, acc[6]);
            acc[7] = fma2(qpd[d], v7, acc[7]);
        }
        uint32_t sb = gring + (uint32_t)(SLOTM * s0 + lane) * 4u;
        #pragma unroll
        for (int k = 0; k < 8; ++k) {
            float lo, hi; unpk(acc[k], lo, hi);
            sts32(sb + (uint32_t)(2 * k)     * (SLOTM * 4), lo);
            sts32(sb + (uint32_t)(2 * k + 1) * (SLOTM * 4), hi);
        }
    };

    // ---- DP state (warps 0-1): lane g in [0,16) of each half-warp owns rows 2g, 2g+1 ----
    const int g    = lane & 15;
    const int wdp  = warp * 2 + (lane >> 4);     // problem index in CTA
    const int ndp  = ng * 4 + wdp;
    // ring byte base for this lane: problem base + row 2g word offset
    const uint32_t ringb = xs_base + (uint32_t)(XWORDS + wdp * RINGW + 2 * g) * 4u;
    float a_prev  = BIGF;                 // D[2g,   jA-1]
    float a_prev2 = BIGF;                 // D[2g,   jA-2]
    float b_prev  = BIGF;                 // D[2g+1, jB-1]
    float u1_prev = (g == 0) ? 0.f : BIGF; // D[2g-1, jA-1]; g==0 seed makes D[0,0]=c00
    float* outA = out + (((size_t)(b * NP + ndp)) * 32 + 2 * g) * LOUT;
    float* outB = outA + LOUT;

    if (is_gen) gen_chunk(0);
    __syncthreads();

    for (int p = 0; p < NPH; ++p) {
        if (is_gen) {
            if (p <= 62) gen_chunk(p + 1);
        } else {
            const int t0 = p * CH;
            const int u  = t0 - 2 * g;           // jA at s=0
            if (p < 2) {
                // head: j may be negative -> force BIG (also kills ring garbage/NaN)
                for (int s = 0; s < CH; ++s) {
                    float u1 = __shfl_up_sync(0xffffffffu, b_prev, 1, 16);
                    if (g == 0) u1 = BIGF;
                    float cA = lds32(ringb + 136u * ((unsigned)(u + s) & 63u));
                    float cB = lds32(ringb + 136u * ((unsigned)(u + s - 1) & 63u) + 4u);
                    float A = cA + fminf(fminf(u1, u1_prev), a_prev);
                    float B = cB + fminf(fminf(a_prev2, b_prev), a_prev);
                    if (u + s < 0)     A = BIGF;
                    if (u + s - 1 < 0) B = BIGF;
                    u1_prev = u1; a_prev2 = a_prev; a_prev = A; b_prev = B;
                }
            } else if (p < 62) {
                // main: all valid, no stores
                #pragma unroll
                for (int s = 0; s < CH; ++s) {
                    float u1 = __shfl_up_sync(0xffffffffu, b_prev, 1, 16);
                    if (g == 0) u1 = BIGF;
                    float cA = lds32(ringb + 136u * ((unsigned)(u + s) & 63u));
                    float cB = lds32(ringb + 136u * ((unsigned)(u + s - 1) & 63u) + 4u);
                    float A = cA + fminf(fminf(u1, u1_prev), a_prev);
                    float B = cB + fminf(fminf(a_prev2, b_prev), a_prev);
                    u1_prev = u1; a_prev2 = a_prev; a_prev = A; b_prev = B;
                }
            } else {
                // tail: guarded stores for j in [992,1024); j>1023 cells are
                // garbage-fed but provably never stored nor feed valid cells
                for (int s = 0; s < CH; ++s) {
                    float u1 = __shfl_up_sync(0xffffffffu, b_prev, 1, 16);
                    if (g == 0) u1 = BIGF;
                    float cA = lds32(ringb + 136u * ((unsigned)(u + s) & 63u));
                    float cB = lds32(ringb + 136u * ((unsigned)(u + s - 1) & 63u) + 4u);
                    float A = cA + fminf(fminf(u1, u1_prev), a_prev);
                    float B = cB + fminf(fminf(a_prev2, b_prev), a_prev);
                    int jA = u + s;
                    unsigned joA = (unsigned)(jA - (LL - LOUT));
                    if (joA < (unsigned)LOUT) outA[joA] = A;
                    unsigned joB = (unsigned)(jA - 1 - (LL - LOUT));
                    if (joB < (unsigned)LOUT) outB[joB] = B;
                    u1_prev = u1; a_prev2 = a_prev; a_prev = A; b_prev = B;
                }
            }
        }
        __syncthreads();
    }
}

extern "C" void kernel_launch(void* const* d_in, const int* in_sizes, int n_in,
                              void* d_out, int out_size)
{
    const float* x     = (const float*)d_in[0];   // [32, 12, 1024]
    const float* patts = (const float*)d_in[1];   // [32, 12, 32]
    float* out         = (float*)d_out;           // [32, 32, 32, 32]

    const int smem = SMEMW * sizeof(float);       // 88080 B -> 2 CTAs/SM
    cudaFuncSetAttribute(dtw_kernel, cudaFuncAttributeMaxDynamicSharedMemorySize, smem);
    dtw_kernel<<<B_ * (NP / 4), TPB, smem>>>(x, patts, out);
}